// round 14
// baseline (speedup 1.0000x reference)
#include <cuda_runtime.h>
#include <math.h>

typedef unsigned long long u64;

// ---------------------------------------------------------------------------
// Packed f32x2 helpers (Blackwell FFMA2 — only reachable via PTX fma.rn.f32x2)
// ---------------------------------------------------------------------------
__device__ __forceinline__ u64 pack2(float x) {
    u64 r; asm("mov.b64 %0, {%1, %1};" : "=l"(r) : "f"(x)); return r;
}
__device__ __forceinline__ void unpack2(u64 v, float& lo, float& hi) {
    asm("mov.b64 {%0, %1}, %2;" : "=f"(lo), "=f"(hi) : "l"(v));
}
__device__ __forceinline__ u64 fma2(u64 a, u64 b, u64 c) {
    u64 d; asm("fma.rn.f32x2 %0, %1, %2, %3;" : "=l"(d) : "l"(a), "l"(b), "l"(c));
    return d;
}

// ---------------------------------------------------------------------------
// Problem constants
// ---------------------------------------------------------------------------
#define IMG_H 1280
#define IMG_W 720
#define NH 64
#define NW 36
#define L_BLOCKS 2304
#define OUT_H 5120
#define OUT_W 2880
#define OUT_PLANE (OUT_H * OUT_W)
#define OUT_IMG (3 * OUT_PLANE)

#define G1_C 16
#define G1_H 640
#define G1_W 360
#define G1_AREA (G1_H * G1_W)
#define G2_C 8
#define G2_H 320
#define G2_W 180
#define G2_AREA (G2_H * G2_W)

// gate1 tiling inside the fused kernel: pooled 8 rows x 6 cols per CTA
#define G1_TH 8
#define G1_TW 6
#define G1_GY (G1_H / G1_TH)     // 80
#define G1_GX (G1_W / G1_TW)     // 60
#define G1_BLOCKS (G1_GY * G1_GX) // 4800

__device__ float g_g1[G1_C * G1_AREA];
__device__ float g_g2[G2_C * G2_AREA];

// ---------------------------------------------------------------------------
// Fused smem: only one path is active per block -> union keeps footprint at
// the light path's 24.4 KB.
// ---------------------------------------------------------------------------
struct SmemLight {
    u64  in2[3][22][36];                 // duplicated input, row stride 36 u64
    float wT[27][48];                    // [k-position][out channel]
    float b[48];
};
struct SmemGate {
    u64  in2[3][18][15];                 // halo tile 18x14, stride 15
    float wT[27][16];
    float b[16];
};
union SmemFused {
    SmemLight l;
    SmemGate  g;
};

// ---------------------------------------------------------------------------
// Fused kernel: blocks [0, L_BLOCKS) = light expert (R12-identical math);
// blocks [L_BLOCKS, L_BLOCKS+G1_BLOCKS) = gate1 conv+maxpool+tanh.
// Single launch -> the work distributor interleaves both workloads on every
// SM: overlap by construction instead of relying on stream concurrency.
// ---------------------------------------------------------------------------
__global__ __launch_bounds__(96)
void fused_kernel(const float* __restrict__ in,
                  const float* __restrict__ wl,
                  const float* __restrict__ bl,
                  const float* __restrict__ w1,
                  const float* __restrict__ b1,
                  float* __restrict__ out)
{
    __shared__ __align__(16) SmemFused sm;
    const int tid = threadIdx.x;

    if (blockIdx.x < L_BLOCKS) {
        // ================= LIGHT PATH (identical math to R12 best) =========
        const int blk = blockIdx.x;
        const int bh = blk / NW;
        const int bw = blk % NW;

        for (int i = tid; i < 27 * 48; i += 96) {
            int k = i / 48, oc = i % 48;
            sm.l.wT[k][oc] = wl[oc * 27 + k];
        }
        if (tid < 48) sm.l.b[tid] = bl[tid];

        for (int i = tid; i < 3 * 22 * 22; i += 96) {
            int x = i % 22;
            int y = (i / 22) % 22;
            int c = i / 484;
            float v = 0.0f;
            if (y >= 1 && y <= 20 && x >= 1 && x <= 20)
                v = in[c * (IMG_H * IMG_W) + (bh * 20 + y - 1) * IMG_W + (bw * 20 + x - 1)];
            sm.l.in2[c][y][x] = pack2(v);
        }
        __syncthreads();

        #pragma unroll 1
        for (int it = 0; it < 5; it++) {
            const int item = tid + 96 * it;
            const int cg  = item / 80;
            const int rem = item % 80;
            const int p   = rem >> 2;
            const int q0  = (rem & 3) * 5;
            const int oc0 = cg * 8;
            const int c_img = oc0 >> 4;
            const int r1a = (oc0 & 15) >> 2;

            u64 acc[5][4];
            {
                u64 b0 = *(const u64*)&sm.l.b[oc0 + 0];
                u64 b1v = *(const u64*)&sm.l.b[oc0 + 2];
                u64 b2 = *(const u64*)&sm.l.b[oc0 + 4];
                u64 b3 = *(const u64*)&sm.l.b[oc0 + 6];
                #pragma unroll
                for (int j = 0; j < 5; j++) {
                    acc[j][0] = b0; acc[j][1] = b1v;
                    acc[j][2] = b2; acc[j][3] = b3;
                }
            }

            #pragma unroll
            for (int ic = 0; ic < 3; ic++) {
                #pragma unroll
                for (int kh = 0; kh < 3; kh++) {
                    u64 xx[7];
                    #pragma unroll
                    for (int c = 0; c < 7; c++)
                        xx[c] = sm.l.in2[ic][p + kh][q0 + c];
                    #pragma unroll
                    for (int kw = 0; kw < 3; kw++) {
                        const float* wp = &sm.l.wT[ic * 9 + kh * 3 + kw][oc0];
                        ulonglong2 wA = *(const ulonglong2*)(wp);
                        ulonglong2 wB = *(const ulonglong2*)(wp + 4);
                        #pragma unroll
                        for (int j = 0; j < 5; j++) {
                            u64 x = xx[j + kw];
                            acc[j][0] = fma2(x, wA.x, acc[j][0]);
                            acc[j][1] = fma2(x, wA.y, acc[j][1]);
                            acc[j][2] = fma2(x, wB.x, acc[j][2]);
                            acc[j][3] = fma2(x, wB.y, acc[j][3]);
                        }
                    }
                }
            }

            #pragma unroll
            for (int j = 0; j < 5; j++) {
                int q = q0 + j;
                size_t base = (size_t)c_img * OUT_PLANE
                            + (size_t)(bh * 80 + p * 4 + r1a) * OUT_W
                            + (bw * 80 + q * 4);
                float4 v;
                unpack2(acc[j][0], v.x, v.y);
                unpack2(acc[j][1], v.z, v.w);
                v.x = fminf(fmaxf(v.x, 0.0f), 0.6f) + 0.4f;
                v.y = fminf(fmaxf(v.y, 0.0f), 0.6f) + 0.4f;
                v.z = fminf(fmaxf(v.z, 0.0f), 0.6f) + 0.4f;
                v.w = fminf(fmaxf(v.w, 0.0f), 0.6f) + 0.4f;
                *reinterpret_cast<float4*>(&out[base]) = v;

                unpack2(acc[j][2], v.x, v.y);
                unpack2(acc[j][3], v.z, v.w);
                v.x = fminf(fmaxf(v.x, 0.0f), 0.6f) + 0.4f;
                v.y = fminf(fmaxf(v.y, 0.0f), 0.6f) + 0.4f;
                v.z = fminf(fmaxf(v.z, 0.0f), 0.6f) + 0.4f;
                v.w = fminf(fmaxf(v.w, 0.0f), 0.6f) + 0.4f;
                *reinterpret_cast<float4*>(&out[base + OUT_W]) = v;
            }
        }
    } else {
        // ================= GATE1 PATH: conv1 + maxpool2 + tanh =============
        const int gblk = blockIdx.x - L_BLOCKS;   // 0..4799
        const int ty0 = (gblk / G1_GX) * G1_TH;   // pooled row base
        const int tx0 = (gblk % G1_GX) * G1_TW;   // pooled col base

        for (int i = tid; i < 27 * 16; i += 96) {
            int k = i >> 4, oc = i & 15;
            sm.g.wT[k][oc] = w1[oc * 27 + k];
        }
        if (tid < 16) sm.g.b[tid] = b1[tid];

        // halo tile: rows 2*ty0-1 .. 2*ty0+16 (18), cols 2*tx0-1 .. 2*tx0+12 (14)
        for (int i = tid; i < 3 * 18 * 14; i += 96) {
            int x = i % 14;
            int y = (i / 14) % 18;
            int c = i / 252;
            int gy = min(max(ty0 * 2 - 1 + y, 0), IMG_H - 1);
            int gx = min(max(tx0 * 2 - 1 + x, 0), IMG_W - 1);
            sm.g.in2[c][y][x] = pack2(in[c * (IMG_H * IMG_W) + gy * IMG_W + gx]);
        }
        __syncthreads();

        // thread = (pixel, channel-half): 48 pixels x 2 halves
        const int half = tid / 48;                // 0/1 -> channels 0-7 / 8-15
        const int pix  = tid - half * 48;
        const int px   = pix % G1_TW;             // 0..5
        const int py   = pix / G1_TW;             // 0..7
        const int oc0  = half * 8;

        u64 acc[2][2][4];
        {
            #pragma unroll
            for (int m = 0; m < 4; m++) {
                u64 b = *(const u64*)&sm.g.b[oc0 + 2 * m];
                acc[0][0][m] = b; acc[0][1][m] = b;
                acc[1][0][m] = b; acc[1][1][m] = b;
            }
        }

        #pragma unroll
        for (int ic = 0; ic < 3; ic++) {
            #pragma unroll
            for (int kh = 0; kh < 3; kh++) {
                u64 xx[2][4];
                #pragma unroll
                for (int dy = 0; dy < 2; dy++)
                    #pragma unroll
                    for (int c = 0; c < 4; c++)
                        xx[dy][c] = sm.g.in2[ic][2 * py + kh + dy][2 * px + c];
                #pragma unroll
                for (int kw = 0; kw < 3; kw++) {
                    const float* wp = &sm.g.wT[ic * 9 + kh * 3 + kw][oc0];
                    ulonglong2 wA = *(const ulonglong2*)(wp);
                    ulonglong2 wB = *(const ulonglong2*)(wp + 4);
                    #pragma unroll
                    for (int dy = 0; dy < 2; dy++)
                        #pragma unroll
                        for (int dx = 0; dx < 2; dx++) {
                            u64 x = xx[dy][dx + kw];
                            acc[dy][dx][0] = fma2(x, wA.x, acc[dy][dx][0]);
                            acc[dy][dx][1] = fma2(x, wA.y, acc[dy][dx][1]);
                            acc[dy][dx][2] = fma2(x, wB.x, acc[dy][dx][2]);
                            acc[dy][dx][3] = fma2(x, wB.y, acc[dy][dx][3]);
                        }
                }
            }
        }

        const int py_g = ty0 + py;
        const int px_g = tx0 + px;
        #pragma unroll
        for (int m = 0; m < 4; m++) {
            float m0 = -1e30f, m1 = -1e30f;
            #pragma unroll
            for (int dy = 0; dy < 2; dy++)
                #pragma unroll
                for (int dx = 0; dx < 2; dx++) {
                    float lo, hi;
                    unpack2(acc[dy][dx][m], lo, hi);
                    m0 = fmaxf(m0, lo);
                    m1 = fmaxf(m1, hi);
                }
            g_g1[(oc0 + 2 * m + 0) * G1_AREA + py_g * G1_W + px_g] = tanhf(m0);
            g_g1[(oc0 + 2 * m + 1) * G1_AREA + py_g * G1_W + px_g] = tanhf(m1);
        }
    }
}

// ---------------------------------------------------------------------------
// Kernel B: gate conv2 + maxpool2 -> g2. 8x8 pooled tile per 64-thread CTA.
// ---------------------------------------------------------------------------
__global__ __launch_bounds__(64)
void gate2_kernel(const float* __restrict__ w2,
                  const float* __restrict__ b2)
{
    __shared__ float s_g[16][18][19];
    __shared__ float s_wT[144][8];

    const int tid = threadIdx.x;
    const int tx = tid & 7, ty = tid >> 3;
    const int ty0 = blockIdx.y * 8;
    const int tx0 = blockIdx.x * 8;

    for (int i = tid; i < 144 * 8; i += 64) {
        int k = i >> 3, oc = i & 7;
        s_wT[k][oc] = w2[oc * 144 + k];
    }

    for (int i = tid; i < 16 * 18 * 18; i += 64) {
        int x = i % 18;
        int y = (i / 18) % 18;
        int c = i / 324;
        int gy = min(max(ty0 * 2 - 1 + y, 0), G1_H - 1);
        int gx = min(max(tx0 * 2 - 1 + x, 0), G1_W - 1);
        s_g[c][y][x] = g_g1[c * G1_AREA + gy * G1_W + gx];
    }
    __syncthreads();

    u64 acc[2][2][4];
    u64 z = pack2(0.0f);
    #pragma unroll
    for (int dy = 0; dy < 2; dy++)
        #pragma unroll
        for (int dx = 0; dx < 2; dx++)
            #pragma unroll
            for (int m = 0; m < 4; m++) acc[dy][dx][m] = z;

    #pragma unroll 1
    for (int ic = 0; ic < 16; ic++) {
        #pragma unroll
        for (int kh = 0; kh < 3; kh++) {
            u64 xx[2][4];
            #pragma unroll
            for (int dy = 0; dy < 2; dy++)
                #pragma unroll
                for (int c = 0; c < 4; c++)
                    xx[dy][c] = pack2(s_g[ic][2 * ty + kh + dy][2 * tx + c]);
            #pragma unroll
            for (int kw = 0; kw < 3; kw++) {
                const float* wp = &s_wT[ic * 9 + kh * 3 + kw][0];
                u64 w0 = *(const u64*)(wp + 0);
                u64 w1 = *(const u64*)(wp + 2);
                u64 w2p = *(const u64*)(wp + 4);
                u64 w3 = *(const u64*)(wp + 6);
                #pragma unroll
                for (int dy = 0; dy < 2; dy++)
                    #pragma unroll
                    for (int dx = 0; dx < 2; dx++) {
                        u64 x = xx[dy][dx + kw];
                        acc[dy][dx][0] = fma2(x, w0, acc[dy][dx][0]);
                        acc[dy][dx][1] = fma2(x, w1, acc[dy][dx][1]);
                        acc[dy][dx][2] = fma2(x, w2p, acc[dy][dx][2]);
                        acc[dy][dx][3] = fma2(x, w3, acc[dy][dx][3]);
                    }
            }
        }
    }

    int py = ty0 + ty;
    int px = tx0 + tx;
    if (py < G2_H && px < G2_W) {
        #pragma unroll
        for (int m = 0; m < 4; m++) {
            float m0 = -1e30f, m1 = -1e30f;
            #pragma unroll
            for (int dy = 0; dy < 2; dy++)
                #pragma unroll
                for (int dx = 0; dx < 2; dx++) {
                    float lo, hi;
                    unpack2(acc[dy][dx][m], lo, hi);
                    m0 = fmaxf(m0, lo);
                    m1 = fmaxf(m1, hi);
                }
            g_g2[(2 * m + 0) * G2_AREA + py * G2_W + px] = m0 + b2[2 * m + 0];
            g_g2[(2 * m + 1) * G2_AREA + py * G2_W + px] = m1 + b2[2 * m + 1];
        }
    }
}

// ---------------------------------------------------------------------------
// Kernel C: gate conv3 (5x5 stride 5) + sigmoid. One warp per output.
// ---------------------------------------------------------------------------
__global__ __launch_bounds__(256)
void gate3_kernel(const float* __restrict__ w3,
                  const float* __restrict__ b3,
                  float* __restrict__ out_cv)
{
    __shared__ float s_w[200];
    int tid = threadIdx.x;
    if (tid < 200) s_w[tid] = w3[tid];
    __syncthreads();

    int lane = tid & 31;
    int o = blockIdx.x * 8 + (tid >> 5);
    if (o >= L_BLOCKS) return;
    int by = o / NW;
    int bx = o % NW;

    float v = 0.0f;
    if (lane < 25) {
        int ky = lane / 5, kx = lane % 5;
        const float* gp = &g_g2[(by * 5 + ky) * G2_W + (bx * 5 + kx)];
        #pragma unroll
        for (int ic = 0; ic < 8; ic++)
            v = fmaf(gp[ic * G2_AREA], s_w[ic * 25 + lane], v);
    }

    v += __shfl_xor_sync(0xffffffffu, v, 16);
    v += __shfl_xor_sync(0xffffffffu, v, 8);
    v += __shfl_xor_sync(0xffffffffu, v, 4);
    v += __shfl_xor_sync(0xffffffffu, v, 2);
    v += __shfl_xor_sync(0xffffffffu, v, 1);

    if (lane == 0)
        out_cv[o] = 1.0f / (1.0f + expf(-(v + b3[0])));
}

// ---------------------------------------------------------------------------
// Launch: single stream. Light + gate1 fused into ONE grid (overlap by
// construction); gate2/gate3 serial after (data dependency on g1/g2).
// ---------------------------------------------------------------------------
extern "C" void kernel_launch(void* const* d_in, const int* in_sizes, int n_in,
                              void* d_out, int out_size)
{
    const float* in = (const float*)d_in[0];
    const float* w1 = (const float*)d_in[1];
    const float* b1 = (const float*)d_in[2];
    const float* w2 = (const float*)d_in[3];
    const float* b2 = (const float*)d_in[4];
    const float* w3 = (const float*)d_in[5];
    const float* b3 = (const float*)d_in[6];
    const float* wl = (const float*)d_in[7];
    const float* bl = (const float*)d_in[8];
    // complex expert weights (d_in[9..14]) are provably dead: sigmoid(x) > 1 never

    float* out = (float*)d_out;

    fused_kernel<<<L_BLOCKS + G1_BLOCKS, 96>>>(in, wl, bl, w1, b1, out);
    gate2_kernel<<<dim3((G2_W + 7) / 8, (G2_H + 7) / 8), 64>>>(w2, b2);
    gate3_kernel<<<L_BLOCKS / 8, 256>>>(w3, b3, out + OUT_IMG);
}

// round 15
// speedup vs baseline: 1.0350x; 1.0350x over previous
#include <cuda_runtime.h>
#include <math.h>

typedef unsigned long long u64;

// ---------------------------------------------------------------------------
// Packed f32x2 helpers (Blackwell FFMA2 — only reachable via PTX fma.rn.f32x2)
// ---------------------------------------------------------------------------
__device__ __forceinline__ u64 pack2(float x) {
    u64 r; asm("mov.b64 %0, {%1, %1};" : "=l"(r) : "f"(x)); return r;
}
__device__ __forceinline__ void unpack2(u64 v, float& lo, float& hi) {
    asm("mov.b64 {%0, %1}, %2;" : "=f"(lo), "=f"(hi) : "l"(v));
}
__device__ __forceinline__ u64 fma2(u64 a, u64 b, u64 c) {
    u64 d; asm("fma.rn.f32x2 %0, %1, %2, %3;" : "=l"(d) : "l"(a), "l"(b), "l"(c));
    return d;
}

// ---------------------------------------------------------------------------
// Problem constants
// ---------------------------------------------------------------------------
#define IMG_H 1280
#define IMG_W 720
#define NH 64
#define NW 36
#define L_BLOCKS 2304
#define OUT_H 5120
#define OUT_W 2880
#define OUT_PLANE (OUT_H * OUT_W)
#define OUT_IMG (3 * OUT_PLANE)

#define G1_C 16
#define G1_H 640
#define G1_W 360
#define G1_AREA (G1_H * G1_W)
#define G2_H 320
#define G2_W 180

// gate1 tiling inside fused kernel 1: pooled 8 rows x 6 cols per CTA
#define G1_TH 8
#define G1_TW 6
#define G1_GY (G1_H / G1_TH)      // 80
#define G1_GX (G1_W / G1_TW)      // 60
#define G1_BLOCKS (G1_GY * G1_GX) // 4800

__device__ float g_g1[G1_C * G1_AREA];

// ---------------------------------------------------------------------------
// Fused smem for kernel 1 (union keeps footprint at the light path's 24.4 KB)
// ---------------------------------------------------------------------------
struct SmemLight {
    u64  in2[3][22][36];
    float wT[27][48];
    float b[48];
};
struct SmemGate {
    u64  in2[3][18][15];
    float wT[27][16];
    float b[16];
};
union SmemFused {
    SmemLight l;
    SmemGate  g;
};

// ---------------------------------------------------------------------------
// Fused kernel 1: blocks [0, L_BLOCKS) = light expert (R12 math, 79.8us alone);
// blocks [L_BLOCKS, +G1_BLOCKS) = gate1 conv+maxpool+tanh -> g_g1.
// (Measured R14: 102.4us for both, i.e. gate1 absorbed at ~22us marginal.)
// ---------------------------------------------------------------------------
__global__ __launch_bounds__(96)
void fused_kernel(const float* __restrict__ in,
                  const float* __restrict__ wl,
                  const float* __restrict__ bl,
                  const float* __restrict__ w1,
                  const float* __restrict__ b1,
                  float* __restrict__ out)
{
    __shared__ __align__(16) SmemFused sm;
    const int tid = threadIdx.x;

    if (blockIdx.x < L_BLOCKS) {
        // ================= LIGHT PATH =================
        const int blk = blockIdx.x;
        const int bh = blk / NW;
        const int bw = blk % NW;

        for (int i = tid; i < 27 * 48; i += 96) {
            int k = i / 48, oc = i % 48;
            sm.l.wT[k][oc] = wl[oc * 27 + k];
        }
        if (tid < 48) sm.l.b[tid] = bl[tid];

        for (int i = tid; i < 3 * 22 * 22; i += 96) {
            int x = i % 22;
            int y = (i / 22) % 22;
            int c = i / 484;
            float v = 0.0f;
            if (y >= 1 && y <= 20 && x >= 1 && x <= 20)
                v = in[c * (IMG_H * IMG_W) + (bh * 20 + y - 1) * IMG_W + (bw * 20 + x - 1)];
            sm.l.in2[c][y][x] = pack2(v);
        }
        __syncthreads();

        #pragma unroll 1
        for (int it = 0; it < 5; it++) {
            const int item = tid + 96 * it;
            const int cg  = item / 80;
            const int rem = item % 80;
            const int p   = rem >> 2;
            const int q0  = (rem & 3) * 5;
            const int oc0 = cg * 8;
            const int c_img = oc0 >> 4;
            const int r1a = (oc0 & 15) >> 2;

            u64 acc[5][4];
            {
                u64 b0 = *(const u64*)&sm.l.b[oc0 + 0];
                u64 b1v = *(const u64*)&sm.l.b[oc0 + 2];
                u64 b2 = *(const u64*)&sm.l.b[oc0 + 4];
                u64 b3 = *(const u64*)&sm.l.b[oc0 + 6];
                #pragma unroll
                for (int j = 0; j < 5; j++) {
                    acc[j][0] = b0; acc[j][1] = b1v;
                    acc[j][2] = b2; acc[j][3] = b3;
                }
            }

            #pragma unroll
            for (int ic = 0; ic < 3; ic++) {
                #pragma unroll
                for (int kh = 0; kh < 3; kh++) {
                    u64 xx[7];
                    #pragma unroll
                    for (int c = 0; c < 7; c++)
                        xx[c] = sm.l.in2[ic][p + kh][q0 + c];
                    #pragma unroll
                    for (int kw = 0; kw < 3; kw++) {
                        const float* wp = &sm.l.wT[ic * 9 + kh * 3 + kw][oc0];
                        ulonglong2 wA = *(const ulonglong2*)(wp);
                        ulonglong2 wB = *(const ulonglong2*)(wp + 4);
                        #pragma unroll
                        for (int j = 0; j < 5; j++) {
                            u64 x = xx[j + kw];
                            acc[j][0] = fma2(x, wA.x, acc[j][0]);
                            acc[j][1] = fma2(x, wA.y, acc[j][1]);
                            acc[j][2] = fma2(x, wB.x, acc[j][2]);
                            acc[j][3] = fma2(x, wB.y, acc[j][3]);
                        }
                    }
                }
            }

            #pragma unroll
            for (int j = 0; j < 5; j++) {
                int q = q0 + j;
                size_t base = (size_t)c_img * OUT_PLANE
                            + (size_t)(bh * 80 + p * 4 + r1a) * OUT_W
                            + (bw * 80 + q * 4);
                float4 v;
                unpack2(acc[j][0], v.x, v.y);
                unpack2(acc[j][1], v.z, v.w);
                v.x = fminf(fmaxf(v.x, 0.0f), 0.6f) + 0.4f;
                v.y = fminf(fmaxf(v.y, 0.0f), 0.6f) + 0.4f;
                v.z = fminf(fmaxf(v.z, 0.0f), 0.6f) + 0.4f;
                v.w = fminf(fmaxf(v.w, 0.0f), 0.6f) + 0.4f;
                *reinterpret_cast<float4*>(&out[base]) = v;

                unpack2(acc[j][2], v.x, v.y);
                unpack2(acc[j][3], v.z, v.w);
                v.x = fminf(fmaxf(v.x, 0.0f), 0.6f) + 0.4f;
                v.y = fminf(fmaxf(v.y, 0.0f), 0.6f) + 0.4f;
                v.z = fminf(fmaxf(v.z, 0.0f), 0.6f) + 0.4f;
                v.w = fminf(fmaxf(v.w, 0.0f), 0.6f) + 0.4f;
                *reinterpret_cast<float4*>(&out[base + OUT_W]) = v;
            }
        }
    } else {
        // ================= GATE1 PATH =================
        const int gblk = blockIdx.x - L_BLOCKS;
        const int ty0 = (gblk / G1_GX) * G1_TH;
        const int tx0 = (gblk % G1_GX) * G1_TW;

        for (int i = tid; i < 27 * 16; i += 96) {
            int k = i >> 4, oc = i & 15;
            sm.g.wT[k][oc] = w1[oc * 27 + k];
        }
        if (tid < 16) sm.g.b[tid] = b1[tid];

        for (int i = tid; i < 3 * 18 * 14; i += 96) {
            int x = i % 14;
            int y = (i / 14) % 18;
            int c = i / 252;
            int gy = min(max(ty0 * 2 - 1 + y, 0), IMG_H - 1);
            int gx = min(max(tx0 * 2 - 1 + x, 0), IMG_W - 1);
            sm.g.in2[c][y][x] = pack2(in[c * (IMG_H * IMG_W) + gy * IMG_W + gx]);
        }
        __syncthreads();

        const int half = tid / 48;
        const int pix  = tid - half * 48;
        const int px   = pix % G1_TW;
        const int py   = pix / G1_TW;
        const int oc0  = half * 8;

        u64 acc[2][2][4];
        {
            #pragma unroll
            for (int m = 0; m < 4; m++) {
                u64 b = *(const u64*)&sm.g.b[oc0 + 2 * m];
                acc[0][0][m] = b; acc[0][1][m] = b;
                acc[1][0][m] = b; acc[1][1][m] = b;
            }
        }

        #pragma unroll
        for (int ic = 0; ic < 3; ic++) {
            #pragma unroll
            for (int kh = 0; kh < 3; kh++) {
                u64 xx[2][4];
                #pragma unroll
                for (int dy = 0; dy < 2; dy++)
                    #pragma unroll
                    for (int c = 0; c < 4; c++)
                        xx[dy][c] = sm.g.in2[ic][2 * py + kh + dy][2 * px + c];
                #pragma unroll
                for (int kw = 0; kw < 3; kw++) {
                    const float* wp = &sm.g.wT[ic * 9 + kh * 3 + kw][oc0];
                    ulonglong2 wA = *(const ulonglong2*)(wp);
                    ulonglong2 wB = *(const ulonglong2*)(wp + 4);
                    #pragma unroll
                    for (int dy = 0; dy < 2; dy++)
                        #pragma unroll
                        for (int dx = 0; dx < 2; dx++) {
                            u64 x = xx[dy][dx + kw];
                            acc[dy][dx][0] = fma2(x, wA.x, acc[dy][dx][0]);
                            acc[dy][dx][1] = fma2(x, wA.y, acc[dy][dx][1]);
                            acc[dy][dx][2] = fma2(x, wB.x, acc[dy][dx][2]);
                            acc[dy][dx][3] = fma2(x, wB.y, acc[dy][dx][3]);
                        }
                }
            }
        }

        const int py_g = ty0 + py;
        const int px_g = tx0 + px;
        #pragma unroll
        for (int m = 0; m < 4; m++) {
            float m0 = -1e30f, m1 = -1e30f;
            #pragma unroll
            for (int dy = 0; dy < 2; dy++)
                #pragma unroll
                for (int dx = 0; dx < 2; dx++) {
                    float lo, hi;
                    unpack2(acc[dy][dx][m], lo, hi);
                    m0 = fmaxf(m0, lo);
                    m1 = fmaxf(m1, hi);
                }
            g_g1[(oc0 + 2 * m + 0) * G1_AREA + py_g * G1_W + px_g] = tanhf(m0);
            g_g1[(oc0 + 2 * m + 1) * G1_AREA + py_g * G1_W + px_g] = tanhf(m1);
        }
    }
}

// ---------------------------------------------------------------------------
// Fused kernel 2: gate2 (conv+maxpool+bias) + gate3 (5x5 s5 conv + sigmoid),
// g2 never touches global memory. One CTA = 2x2 gate3 outputs = 10x10 g2
// tile = 20x20 conv2 tile = 22x22x16 g1 halo. 128 threads, 576 CTAs.
// ---------------------------------------------------------------------------
__global__ __launch_bounds__(128)
void gate23_kernel(const float* __restrict__ w2,
                   const float* __restrict__ b2,
                   const float* __restrict__ w3,
                   const float* __restrict__ b3,
                   float* __restrict__ out_cv)
{
    __shared__ float s_g1[16][22][23];   // g1 halo tile (32.4 KB)
    __shared__ float s_wT[144][8];       // conv2 weights transposed
    __shared__ float s_g2[8][10][12];    // g2 tile (never global)
    __shared__ float s_w3[200];
    __shared__ float s_b2[8];

    const int tid = threadIdx.x;
    const int by0 = blockIdx.y * 2;      // gate3 output row base (0..62)
    const int bx0 = blockIdx.x * 2;      // gate3 output col base (0..34)

    for (int i = tid; i < 144 * 8; i += 128) {
        int k = i >> 3, oc = i & 7;
        s_wT[k][oc] = w2[oc * 144 + k];
    }
    for (int i = tid; i < 200; i += 128) s_w3[i] = w3[i];
    if (tid < 8) s_b2[tid] = b2[tid];

    // g1 halo: conv2 rows [by0*10-1, +22), cols [bx0*10-1, +22), edge-clamped
    for (int i = tid; i < 16 * 22 * 22; i += 128) {
        int x = i % 22;
        int y = (i / 22) % 22;
        int c = i / 484;
        int gy = min(max(by0 * 10 - 1 + y, 0), G1_H - 1);
        int gx = min(max(bx0 * 10 - 1 + x, 0), G1_W - 1);
        s_g1[c][y][x] = g_g1[c * G1_AREA + gy * G1_W + gx];
    }
    __syncthreads();

    // Phase 1: conv2 + maxpool + bias. Threads 0..99 = pooled pixel (pp,qq).
    if (tid < 100) {
        const int qq = tid % 10;
        const int pp = tid / 10;

        u64 acc[2][2][4];
        u64 z = pack2(0.0f);
        #pragma unroll
        for (int dy = 0; dy < 2; dy++)
            #pragma unroll
            for (int dx = 0; dx < 2; dx++)
                #pragma unroll
                for (int m = 0; m < 4; m++) acc[dy][dx][m] = z;

        #pragma unroll 1
        for (int ic = 0; ic < 16; ic++) {
            #pragma unroll
            for (int kh = 0; kh < 3; kh++) {
                u64 xx[2][4];
                #pragma unroll
                for (int dy = 0; dy < 2; dy++)
                    #pragma unroll
                    for (int c = 0; c < 4; c++)
                        xx[dy][c] = pack2(s_g1[ic][2 * pp + kh + dy][2 * qq + c]);
                #pragma unroll
                for (int kw = 0; kw < 3; kw++) {
                    const float* wp = &s_wT[ic * 9 + kh * 3 + kw][0];
                    u64 w0 = *(const u64*)(wp + 0);
                    u64 w1 = *(const u64*)(wp + 2);
                    u64 w2v = *(const u64*)(wp + 4);
                    u64 w3v = *(const u64*)(wp + 6);
                    #pragma unroll
                    for (int dy = 0; dy < 2; dy++)
                        #pragma unroll
                        for (int dx = 0; dx < 2; dx++) {
                            u64 x = xx[dy][dx + kw];
                            acc[dy][dx][0] = fma2(x, w0, acc[dy][dx][0]);
                            acc[dy][dx][1] = fma2(x, w1, acc[dy][dx][1]);
                            acc[dy][dx][2] = fma2(x, w2v, acc[dy][dx][2]);
                            acc[dy][dx][3] = fma2(x, w3v, acc[dy][dx][3]);
                        }
                }
            }
        }

        #pragma unroll
        for (int m = 0; m < 4; m++) {
            float m0 = -1e30f, m1 = -1e30f;
            #pragma unroll
            for (int dy = 0; dy < 2; dy++)
                #pragma unroll
                for (int dx = 0; dx < 2; dx++) {
                    float lo, hi;
                    unpack2(acc[dy][dx][m], lo, hi);
                    m0 = fmaxf(m0, lo);
                    m1 = fmaxf(m1, hi);
                }
            s_g2[2 * m + 0][pp][qq] = m0 + s_b2[2 * m + 0];
            s_g2[2 * m + 1][pp][qq] = m1 + s_b2[2 * m + 1];
        }
    }
    __syncthreads();

    // Phase 2: gate3. Warp w -> output (by0 + w/2, bx0 + w%2).
    const int warp = tid >> 5;
    const int lane = tid & 31;
    const int dy = warp >> 1;
    const int dx = warp & 1;

    float v = 0.0f;
    if (lane < 25) {
        int ky = lane / 5, kx = lane % 5;
        #pragma unroll
        for (int ic = 0; ic < 8; ic++)
            v = fmaf(s_g2[ic][dy * 5 + ky][dx * 5 + kx], s_w3[ic * 25 + lane], v);
    }
    v += __shfl_xor_sync(0xffffffffu, v, 16);
    v += __shfl_xor_sync(0xffffffffu, v, 8);
    v += __shfl_xor_sync(0xffffffffu, v, 4);
    v += __shfl_xor_sync(0xffffffffu, v, 2);
    v += __shfl_xor_sync(0xffffffffu, v, 1);

    if (lane == 0)
        out_cv[(by0 + dy) * NW + (bx0 + dx)] = 1.0f / (1.0f + expf(-(v + b3[0])));
}

// ---------------------------------------------------------------------------
// Launch: two kernels total. fused (light+gate1), then gate23.
// ---------------------------------------------------------------------------
extern "C" void kernel_launch(void* const* d_in, const int* in_sizes, int n_in,
                              void* d_out, int out_size)
{
    const float* in = (const float*)d_in[0];
    const float* w1 = (const float*)d_in[1];
    const float* b1 = (const float*)d_in[2];
    const float* w2 = (const float*)d_in[3];
    const float* b2 = (const float*)d_in[4];
    const float* w3 = (const float*)d_in[5];
    const float* b3 = (const float*)d_in[6];
    const float* wl = (const float*)d_in[7];
    const float* bl = (const float*)d_in[8];
    // complex expert weights (d_in[9..14]) are provably dead: sigmoid(x) > 1 never

    float* out = (float*)d_out;

    fused_kernel<<<L_BLOCKS + G1_BLOCKS, 96>>>(in, wl, bl, w1, b1, out);
    gate23_kernel<<<dim3(NW / 2, NH / 2), 128>>>(w2, b2, w3, b3, out + OUT_IMG);
}

// round 16
// speedup vs baseline: 1.0480x; 1.0125x over previous
#include <cuda_runtime.h>
#include <math.h>

typedef unsigned long long u64;

// ---------------------------------------------------------------------------
// Packed f32x2 helpers (Blackwell FFMA2 — only reachable via PTX fma.rn.f32x2)
// ---------------------------------------------------------------------------
__device__ __forceinline__ u64 pack2(float x) {
    u64 r; asm("mov.b64 %0, {%1, %1};" : "=l"(r) : "f"(x)); return r;
}
__device__ __forceinline__ void unpack2(u64 v, float& lo, float& hi) {
    asm("mov.b64 {%0, %1}, %2;" : "=f"(lo), "=f"(hi) : "l"(v));
}
__device__ __forceinline__ u64 fma2(u64 a, u64 b, u64 c) {
    u64 d; asm("fma.rn.f32x2 %0, %1, %2, %3;" : "=l"(d) : "l"(a), "l"(b), "l"(c));
    return d;
}

// ---------------------------------------------------------------------------
// Problem constants
// ---------------------------------------------------------------------------
#define IMG_H 1280
#define IMG_W 720
#define NH 64
#define NW 36
#define L_BLOCKS 2304
#define OUT_H 5120
#define OUT_W 2880
#define OUT_PLANE (OUT_H * OUT_W)
#define OUT_IMG (3 * OUT_PLANE)

#define G1_C 16
#define G1_H 640
#define G1_W 360
#define G1_AREA (G1_H * G1_W)

// gate1 tiling inside fused kernel 1: pooled 8 rows x 6 cols per CTA
#define G1_TH 8
#define G1_TW 6
#define G1_GY (G1_H / G1_TH)      // 80
#define G1_GX (G1_W / G1_TW)      // 60
#define G1_BLOCKS (G1_GY * G1_GX) // 4800

__device__ float g_g1[G1_C * G1_AREA];

// ---------------------------------------------------------------------------
// Fused smem for kernel 1 (union keeps footprint at the light path's 24.4 KB)
// ---------------------------------------------------------------------------
struct SmemLight {
    u64  in2[3][22][36];
    float wT[27][48];
    float b[48];
};
struct SmemGate {
    u64  in2[3][18][15];
    float wT[27][16];
    float b[16];
};
union SmemFused {
    SmemLight l;
    SmemGate  g;
};

// ---------------------------------------------------------------------------
// Fused kernel 1: blocks [0, L_BLOCKS) = light expert; blocks
// [L_BLOCKS, +G1_BLOCKS) = gate1 conv+maxpool+tanh -> g_g1.
// (Measured R14/R15: 102.4us for both.)
// ---------------------------------------------------------------------------
__global__ __launch_bounds__(96)
void fused_kernel(const float* __restrict__ in,
                  const float* __restrict__ wl,
                  const float* __restrict__ bl,
                  const float* __restrict__ w1,
                  const float* __restrict__ b1,
                  float* __restrict__ out)
{
    __shared__ __align__(16) SmemFused sm;
    const int tid = threadIdx.x;

    if (blockIdx.x < L_BLOCKS) {
        // ================= LIGHT PATH =================
        const int blk = blockIdx.x;
        const int bh = blk / NW;
        const int bw = blk % NW;

        for (int i = tid; i < 27 * 48; i += 96) {
            int k = i / 48, oc = i % 48;
            sm.l.wT[k][oc] = wl[oc * 27 + k];
        }
        if (tid < 48) sm.l.b[tid] = bl[tid];

        for (int i = tid; i < 3 * 22 * 22; i += 96) {
            int x = i % 22;
            int y = (i / 22) % 22;
            int c = i / 484;
            float v = 0.0f;
            if (y >= 1 && y <= 20 && x >= 1 && x <= 20)
                v = in[c * (IMG_H * IMG_W) + (bh * 20 + y - 1) * IMG_W + (bw * 20 + x - 1)];
            sm.l.in2[c][y][x] = pack2(v);
        }
        __syncthreads();

        #pragma unroll 1
        for (int it = 0; it < 5; it++) {
            const int item = tid + 96 * it;
            const int cg  = item / 80;
            const int rem = item % 80;
            const int p   = rem >> 2;
            const int q0  = (rem & 3) * 5;
            const int oc0 = cg * 8;
            const int c_img = oc0 >> 4;
            const int r1a = (oc0 & 15) >> 2;

            u64 acc[5][4];
            {
                u64 b0 = *(const u64*)&sm.l.b[oc0 + 0];
                u64 b1v = *(const u64*)&sm.l.b[oc0 + 2];
                u64 b2 = *(const u64*)&sm.l.b[oc0 + 4];
                u64 b3 = *(const u64*)&sm.l.b[oc0 + 6];
                #pragma unroll
                for (int j = 0; j < 5; j++) {
                    acc[j][0] = b0; acc[j][1] = b1v;
                    acc[j][2] = b2; acc[j][3] = b3;
                }
            }

            #pragma unroll
            for (int ic = 0; ic < 3; ic++) {
                #pragma unroll
                for (int kh = 0; kh < 3; kh++) {
                    u64 xx[7];
                    #pragma unroll
                    for (int c = 0; c < 7; c++)
                        xx[c] = sm.l.in2[ic][p + kh][q0 + c];
                    #pragma unroll
                    for (int kw = 0; kw < 3; kw++) {
                        const float* wp = &sm.l.wT[ic * 9 + kh * 3 + kw][oc0];
                        ulonglong2 wA = *(const ulonglong2*)(wp);
                        ulonglong2 wB = *(const ulonglong2*)(wp + 4);
                        #pragma unroll
                        for (int j = 0; j < 5; j++) {
                            u64 x = xx[j + kw];
                            acc[j][0] = fma2(x, wA.x, acc[j][0]);
                            acc[j][1] = fma2(x, wA.y, acc[j][1]);
                            acc[j][2] = fma2(x, wB.x, acc[j][2]);
                            acc[j][3] = fma2(x, wB.y, acc[j][3]);
                        }
                    }
                }
            }

            #pragma unroll
            for (int j = 0; j < 5; j++) {
                int q = q0 + j;
                size_t base = (size_t)c_img * OUT_PLANE
                            + (size_t)(bh * 80 + p * 4 + r1a) * OUT_W
                            + (bw * 80 + q * 4);
                float4 v;
                unpack2(acc[j][0], v.x, v.y);
                unpack2(acc[j][1], v.z, v.w);
                v.x = fminf(fmaxf(v.x, 0.0f), 0.6f) + 0.4f;
                v.y = fminf(fmaxf(v.y, 0.0f), 0.6f) + 0.4f;
                v.z = fminf(fmaxf(v.z, 0.0f), 0.6f) + 0.4f;
                v.w = fminf(fmaxf(v.w, 0.0f), 0.6f) + 0.4f;
                *reinterpret_cast<float4*>(&out[base]) = v;

                unpack2(acc[j][2], v.x, v.y);
                unpack2(acc[j][3], v.z, v.w);
                v.x = fminf(fmaxf(v.x, 0.0f), 0.6f) + 0.4f;
                v.y = fminf(fmaxf(v.y, 0.0f), 0.6f) + 0.4f;
                v.z = fminf(fmaxf(v.z, 0.0f), 0.6f) + 0.4f;
                v.w = fminf(fmaxf(v.w, 0.0f), 0.6f) + 0.4f;
                *reinterpret_cast<float4*>(&out[base + OUT_W]) = v;
            }
        }
    } else {
        // ================= GATE1 PATH =================
        const int gblk = blockIdx.x - L_BLOCKS;
        const int ty0 = (gblk / G1_GX) * G1_TH;
        const int tx0 = (gblk % G1_GX) * G1_TW;

        for (int i = tid; i < 27 * 16; i += 96) {
            int k = i >> 4, oc = i & 15;
            sm.g.wT[k][oc] = w1[oc * 27 + k];
        }
        if (tid < 16) sm.g.b[tid] = b1[tid];

        for (int i = tid; i < 3 * 18 * 14; i += 96) {
            int x = i % 14;
            int y = (i / 14) % 18;
            int c = i / 252;
            int gy = min(max(ty0 * 2 - 1 + y, 0), IMG_H - 1);
            int gx = min(max(tx0 * 2 - 1 + x, 0), IMG_W - 1);
            sm.g.in2[c][y][x] = pack2(in[c * (IMG_H * IMG_W) + gy * IMG_W + gx]);
        }
        __syncthreads();

        const int half = tid / 48;
        const int pix  = tid - half * 48;
        const int px   = pix % G1_TW;
        const int py   = pix / G1_TW;
        const int oc0  = half * 8;

        u64 acc[2][2][4];
        {
            #pragma unroll
            for (int m = 0; m < 4; m++) {
                u64 b = *(const u64*)&sm.g.b[oc0 + 2 * m];
                acc[0][0][m] = b; acc[0][1][m] = b;
                acc[1][0][m] = b; acc[1][1][m] = b;
            }
        }

        #pragma unroll
        for (int ic = 0; ic < 3; ic++) {
            #pragma unroll
            for (int kh = 0; kh < 3; kh++) {
                u64 xx[2][4];
                #pragma unroll
                for (int dy = 0; dy < 2; dy++)
                    #pragma unroll
                    for (int c = 0; c < 4; c++)
                        xx[dy][c] = sm.g.in2[ic][2 * py + kh + dy][2 * px + c];
                #pragma unroll
                for (int kw = 0; kw < 3; kw++) {
                    const float* wp = &sm.g.wT[ic * 9 + kh * 3 + kw][oc0];
                    ulonglong2 wA = *(const ulonglong2*)(wp);
                    ulonglong2 wB = *(const ulonglong2*)(wp + 4);
                    #pragma unroll
                    for (int dy = 0; dy < 2; dy++)
                        #pragma unroll
                        for (int dx = 0; dx < 2; dx++) {
                            u64 x = xx[dy][dx + kw];
                            acc[dy][dx][0] = fma2(x, wA.x, acc[dy][dx][0]);
                            acc[dy][dx][1] = fma2(x, wA.y, acc[dy][dx][1]);
                            acc[dy][dx][2] = fma2(x, wB.x, acc[dy][dx][2]);
                            acc[dy][dx][3] = fma2(x, wB.y, acc[dy][dx][3]);
                        }
                }
            }
        }

        const int py_g = ty0 + py;
        const int px_g = tx0 + px;
        #pragma unroll
        for (int m = 0; m < 4; m++) {
            float m0 = -1e30f, m1 = -1e30f;
            #pragma unroll
            for (int dy = 0; dy < 2; dy++)
                #pragma unroll
                for (int dx = 0; dx < 2; dx++) {
                    float lo, hi;
                    unpack2(acc[dy][dx][m], lo, hi);
                    m0 = fmaxf(m0, lo);
                    m1 = fmaxf(m1, hi);
                }
            g_g1[(oc0 + 2 * m + 0) * G1_AREA + py_g * G1_W + px_g] = tanhf(m0);
            g_g1[(oc0 + 2 * m + 1) * G1_AREA + py_g * G1_W + px_g] = tanhf(m1);
        }
    }
}

// ---------------------------------------------------------------------------
// Fused kernel 2 (v2): gate2+gate3, g2 never global. CTA = 2x1 gate3 outputs
// -> 1152 CTAs (2x R15 grid), halo 22x12x16 = 18.3 KB (vs 42 KB), phase 1 =
// 100 threads x half the work (4 channels each). Per-ic 4x4 input patch
// loaded ONCE and reused across kh (16 pack2 vs 24).
// ---------------------------------------------------------------------------
__global__ __launch_bounds__(128)
void gate23_kernel(const float* __restrict__ w2,
                   const float* __restrict__ b2,
                   const float* __restrict__ w3,
                   const float* __restrict__ b3,
                   float* __restrict__ out_cv)
{
    __shared__ float s_g1[16][22][13];   // g1 halo tile 22x12, pad 13 (18.3 KB)
    __shared__ float s_wT[144][8];       // conv2 weights transposed
    __shared__ float s_g2[8][10][6];     // g2 tile 10x5 (never global)
    __shared__ float s_w3[200];
    __shared__ float s_b2[8];

    const int tid = threadIdx.x;
    const int by0 = blockIdx.y * 2;      // gate3 output rows by0, by0+1
    const int bx  = blockIdx.x;          // gate3 output col

    for (int i = tid; i < 144 * 8; i += 128) {
        int k = i >> 3, oc = i & 7;
        s_wT[k][oc] = w2[oc * 144 + k];
    }
    for (int i = tid; i < 200; i += 128) s_w3[i] = w3[i];
    if (tid < 8) s_b2[tid] = b2[tid];

    // g1 halo: rows [by0*10-1, +22), cols [bx*10-1, +12), edge-clamped
    for (int i = tid; i < 16 * 22 * 12; i += 128) {
        int x = i % 12;
        int y = (i / 12) % 22;
        int c = i / 264;
        int gy = min(max(by0 * 10 - 1 + y, 0), G1_H - 1);
        int gx = min(max(bx * 10 - 1 + x, 0), G1_W - 1);
        s_g1[c][y][x] = g_g1[c * G1_AREA + gy * G1_W + gx];
    }
    __syncthreads();

    // Phase 1: conv2 + maxpool + bias. thread = (pooled px, channel half):
    // 50 px (10 rows x 5 cols) x 2 halves = 100 active threads.
    if (tid < 100) {
        const int half = tid / 50;           // 0 -> ch 0-3, 1 -> ch 4-7
        const int idx  = tid - half * 50;
        const int pp   = idx / 5;            // 0..9
        const int qq   = idx % 5;            // 0..4
        const int oc0  = half * 4;

        u64 acc[2][2][2];
        u64 z = pack2(0.0f);
        #pragma unroll
        for (int dy = 0; dy < 2; dy++)
            #pragma unroll
            for (int dx = 0; dx < 2; dx++) {
                acc[dy][dx][0] = z; acc[dy][dx][1] = z;
            }

        #pragma unroll 1
        for (int ic = 0; ic < 16; ic++) {
            // load the 4x4 patch once, reuse across kh
            u64 xx[4][4];
            #pragma unroll
            for (int r = 0; r < 4; r++)
                #pragma unroll
                for (int c = 0; c < 4; c++)
                    xx[r][c] = pack2(s_g1[ic][2 * pp + r][2 * qq + c]);
            #pragma unroll
            for (int kh = 0; kh < 3; kh++) {
                #pragma unroll
                for (int kw = 0; kw < 3; kw++) {
                    const float* wp = &s_wT[ic * 9 + kh * 3 + kw][oc0];
                    ulonglong2 wA = *(const ulonglong2*)(wp);  // 2 pairs (4 ch)
                    #pragma unroll
                    for (int dy = 0; dy < 2; dy++)
                        #pragma unroll
                        for (int dx = 0; dx < 2; dx++) {
                            u64 x = xx[kh + dy][kw + dx];
                            acc[dy][dx][0] = fma2(x, wA.x, acc[dy][dx][0]);
                            acc[dy][dx][1] = fma2(x, wA.y, acc[dy][dx][1]);
                        }
                }
            }
        }

        #pragma unroll
        for (int m = 0; m < 2; m++) {
            float m0 = -1e30f, m1 = -1e30f;
            #pragma unroll
            for (int dy = 0; dy < 2; dy++)
                #pragma unroll
                for (int dx = 0; dx < 2; dx++) {
                    float lo, hi;
                    unpack2(acc[dy][dx][m], lo, hi);
                    m0 = fmaxf(m0, lo);
                    m1 = fmaxf(m1, hi);
                }
            s_g2[oc0 + 2 * m + 0][pp][qq] = m0 + s_b2[oc0 + 2 * m + 0];
            s_g2[oc0 + 2 * m + 1][pp][qq] = m1 + s_b2[oc0 + 2 * m + 1];
        }
    }
    __syncthreads();

    // Phase 2: gate3. Warp 0 -> output (by0, bx), warp 1 -> (by0+1, bx).
    const int warp = tid >> 5;
    const int lane = tid & 31;
    if (warp < 2) {
        float v = 0.0f;
        if (lane < 25) {
            int ky = lane / 5, kx = lane % 5;
            #pragma unroll
            for (int ic = 0; ic < 8; ic++)
                v = fmaf(s_g2[ic][warp * 5 + ky][kx], s_w3[ic * 25 + lane], v);
        }
        v += __shfl_xor_sync(0xffffffffu, v, 16);
        v += __shfl_xor_sync(0xffffffffu, v, 8);
        v += __shfl_xor_sync(0xffffffffu, v, 4);
        v += __shfl_xor_sync(0xffffffffu, v, 2);
        v += __shfl_xor_sync(0xffffffffu, v, 1);

        if (lane == 0)
            out_cv[(by0 + warp) * NW + bx] = 1.0f / (1.0f + expf(-(v + b3[0])));
    }
}

// ---------------------------------------------------------------------------
// Launch: two kernels total. fused (light+gate1), then gate23 v2.
// ---------------------------------------------------------------------------
extern "C" void kernel_launch(void* const* d_in, const int* in_sizes, int n_in,
                              void* d_out, int out_size)
{
    const float* in = (const float*)d_in[0];
    const float* w1 = (const float*)d_in[1];
    const float* b1 = (const float*)d_in[2];
    const float* w2 = (const float*)d_in[3];
    const float* b2 = (const float*)d_in[4];
    const float* w3 = (const float*)d_in[5];
    const float* b3 = (const float*)d_in[6];
    const float* wl = (const float*)d_in[7];
    const float* bl = (const float*)d_in[8];
    // complex expert weights (d_in[9..14]) are provably dead: sigmoid(x) > 1 never

    float* out = (float*)d_out;

    fused_kernel<<<L_BLOCKS + G1_BLOCKS, 96>>>(in, wl, bl, w1, b1, out);
    gate23_kernel<<<dim3(NW, NH / 2), 128>>>(w2, b2, w3, b3, out + OUT_IMG);
}